// round 1
// baseline (speedup 1.0000x reference)
#include <cuda_runtime.h>
#include <math.h>

// ---------------- problem constants ----------------
#define BB   2
#define CC   320
#define NNODE 1024
#define NH   8
#define DH   40
#define LLAYERS 2
#define C2   640
#define C3   960
#define AA   16
#define EPD  64

#define EDGE_SCALE 0.17677669529663687f  // 32^-0.5
#define ATTN_SCALE 0.15811388300841897f  // 40^-0.5
#define LN_EPS 1e-5f

// ---------------- scratch (static device globals; no runtime alloc) ----------------
static __device__ float g_node[BB * NNODE * CC];        // [B,N,C]
static __device__ float g_qk[BB * NNODE * C2];          // [B,N,2C]
static __device__ float g_y[BB * NNODE * CC];           // gln output
static __device__ float g_qkv[BB * NNODE * C3];         // [B,N,3C]
static __device__ float g_edge[BB * NNODE * NNODE];     // [B,N,N]
static __device__ float g_ednew[BB * NNODE * NNODE];    // [B,N,N]
static __device__ float g_attn[(size_t)BB * NH * NNODE * NNODE]; // 64MB
static __device__ float g_nodeout[BB * NNODE * CC];
static __device__ float g_s[BB * CC];

// ---------------- reductions ----------------
__device__ __forceinline__ float blockReduceSum(float v, float* sdata) {
    int tid = threadIdx.x;
    sdata[tid] = v;
    __syncthreads();
    for (int s = blockDim.x >> 1; s > 0; s >>= 1) {
        if (tid < s) sdata[tid] += sdata[tid + s];
        __syncthreads();
    }
    float r = sdata[0];
    __syncthreads();
    return r;
}

__device__ __forceinline__ float blockReduceMax(float v, float* sdata) {
    int tid = threadIdx.x;
    sdata[tid] = v;
    __syncthreads();
    for (int s = blockDim.x >> 1; s > 0; s >>= 1) {
        if (tid < s) sdata[tid] = fmaxf(sdata[tid], sdata[tid + s]);
        __syncthreads();
    }
    float r = sdata[0];
    __syncthreads();
    return r;
}

// ---------------- transpose in: x[B,C,N] -> node[B,N,C] ----------------
__global__ void k_tin(const float* __restrict__ x, float* __restrict__ node) {
    __shared__ float t[32][33];
    int b = blockIdx.z;
    int c0 = blockIdx.y * 32, n0 = blockIdx.x * 32;
#pragma unroll
    for (int i = 0; i < 4; i++)
        t[threadIdx.y + i * 8][threadIdx.x] =
            x[((size_t)b * CC + c0 + threadIdx.y + i * 8) * NNODE + n0 + threadIdx.x];
    __syncthreads();
#pragma unroll
    for (int i = 0; i < 4; i++)
        node[((size_t)b * NNODE + n0 + threadIdx.y + i * 8) * CC + c0 + threadIdx.x] =
            t[threadIdx.x][threadIdx.y + i * 8];
}

// ---------------- transpose out: node[B,N,C] -> out[B,C,N] ----------------
__global__ void k_tout(const float* __restrict__ node, float* __restrict__ out) {
    __shared__ float t[32][33];
    int b = blockIdx.z;
    int c0 = blockIdx.y * 32, n0 = blockIdx.x * 32;
#pragma unroll
    for (int i = 0; i < 4; i++)
        t[threadIdx.y + i * 8][threadIdx.x] =
            node[((size_t)b * NNODE + n0 + threadIdx.y + i * 8) * CC + c0 + threadIdx.x];
    __syncthreads();
#pragma unroll
    for (int i = 0; i < 4; i++)
        out[((size_t)b * CC + c0 + threadIdx.y + i * 8) * NNODE + n0 + threadIdx.x] =
            t[threadIdx.x][threadIdx.y + i * 8];
}

// ---------------- s[b,c] = sum_a (da_prior @ fcp_w.T + fcp_b) ----------------
__global__ void k_prior(const float* __restrict__ da, const float* __restrict__ w,
                        const float* __restrict__ bfc, float* __restrict__ s) {
    int t = blockIdx.x * blockDim.x + threadIdx.x;
    if (t >= BB * CC) return;
    int b = t / CC, c = t % CC;
    float acc = (float)AA * bfc[c];
    for (int e = 0; e < EPD; e++) {
        float sa = 0.f;
#pragma unroll
        for (int a = 0; a < AA; a++) sa += da[((size_t)b * AA + a) * EPD + e];
        acc += sa * w[c * EPD + e];
    }
    s[t] = acc;
}

// ---------------- generic NT GEMM: C[m,n] = alpha * sum_k A[m,k]*W[n,k] (+bias[n]) ----
// 64x64 tile, 4x4 per thread, TK=16. Dims assumed divisible by 64/16.
__global__ void k_gemm_nt(const float* __restrict__ A, int lda, size_t sA,
                          const float* __restrict__ W, int ldw, size_t sW,
                          float* __restrict__ Cc, int ldc, size_t sC,
                          int K, float alpha, const float* __restrict__ bias) {
    int bz = blockIdx.z;
    A += (size_t)bz * sA;
    W += (size_t)bz * sW;
    Cc += (size_t)bz * sC;
    __shared__ __align__(16) float As[16][68];
    __shared__ __align__(16) float Ws[16][68];
    int m0 = blockIdx.y * 64, n0 = blockIdx.x * 64;
    int tid = threadIdx.y * 16 + threadIdx.x;
    float acc[4][4] = {};
    for (int k0 = 0; k0 < K; k0 += 16) {
        for (int i = tid; i < 64 * 16; i += 256) {
            int r = i >> 4, kk = i & 15;
            As[kk][r] = A[(size_t)(m0 + r) * lda + k0 + kk];
            Ws[kk][r] = W[(size_t)(n0 + r) * ldw + k0 + kk];
        }
        __syncthreads();
#pragma unroll
        for (int kk = 0; kk < 16; kk++) {
            float4 a4 = *reinterpret_cast<const float4*>(&As[kk][threadIdx.y * 4]);
            float4 b4 = *reinterpret_cast<const float4*>(&Ws[kk][threadIdx.x * 4]);
            float av[4] = {a4.x, a4.y, a4.z, a4.w};
            float bv[4] = {b4.x, b4.y, b4.z, b4.w};
#pragma unroll
            for (int i = 0; i < 4; i++)
#pragma unroll
                for (int j = 0; j < 4; j++) acc[i][j] += av[i] * bv[j];
        }
        __syncthreads();
    }
#pragma unroll
    for (int i = 0; i < 4; i++) {
        int m = m0 + threadIdx.y * 4 + i;
#pragma unroll
        for (int j = 0; j < 4; j++) {
            int n = n0 + threadIdx.x * 4 + j;
            float v = alpha * acc[i][j];
            if (bias) v += bias[n];
            Cc[(size_t)m * ldc + n] = v;
        }
    }
}

// ---------------- row softmax in-place on [B*N, N] ----------------
__global__ void k_row_softmax(float* __restrict__ E) {
    size_t off = (size_t)blockIdx.x * NNODE;
    __shared__ float row[NNODE];
    __shared__ float red[256];
    int tid = threadIdx.x;
    float lmax = -3.4e38f;
    for (int i = tid; i < NNODE; i += 256) {
        float v = E[off + i];
        row[i] = v;
        lmax = fmaxf(lmax, v);
    }
    float mx = blockReduceMax(lmax, red);
    float ls = 0.f;
    for (int i = tid; i < NNODE; i += 256) ls += expf(row[i] - mx);
    float Z = blockReduceSum(ls, red);
    float invZ = 1.f / Z;
    for (int i = tid; i < NNODE; i += 256) E[off + i] = expf(row[i] - mx) * invZ;
}

// ---------------- fused LN1 + graph-mix + LN2 ----------------
__global__ void k_ln_fuse(const float* __restrict__ node, const float* __restrict__ edge,
                          const float* __restrict__ s,
                          const float* __restrict__ g1, const float* __restrict__ b1,
                          const float* __restrict__ g2, const float* __restrict__ b2,
                          float* __restrict__ y) {
    int bn = blockIdx.x;
    int b = bn >> 10, n = bn & 1023;
    __shared__ float row[CC];
    __shared__ float red[256];
    int tid = threadIdx.x;
    const float* xr = node + (size_t)bn * CC;
    float lsum = 0.f, lsq = 0.f;
    for (int c = tid; c < CC; c += 256) {
        float v = xr[c];
        row[c] = v;
        lsum += v;
        lsq += v * v;
    }
    float sum = blockReduceSum(lsum, red);
    float sq = blockReduceSum(lsq, red);
    float mean = sum * (1.f / CC);
    float var = sq * (1.f / CC) - mean * mean;
    float inv = rsqrtf(var + LN_EPS);
    float diag = edge[((size_t)b * NNODE + n) * NNODE + n];
    lsum = 0.f;
    lsq = 0.f;
    for (int c = tid; c < CC; c += 256) {
        float nt = (row[c] - mean) * inv * g1[c] + b1[c];
        float n2 = diag * nt * s[b * CC + c] + nt;
        row[c] = n2;
        lsum += n2;
        lsq += n2 * n2;
    }
    float sum2 = blockReduceSum(lsum, red);
    float sq2 = blockReduceSum(lsq, red);
    float mean2 = sum2 * (1.f / CC);
    float var2 = sq2 * (1.f / CC) - mean2 * mean2;
    float inv2 = rsqrtf(var2 + LN_EPS);
    float* yr = y + (size_t)bn * CC;
    for (int c = tid; c < CC; c += 256)
        yr[c] = (row[c] - mean2) * inv2 * g2[c] + b2[c];
}

// ---------------- attn logits: attn[b,h,n,m] = SCALE*q.k + exp_w[h]*edge + exp_b[h] ----
__global__ void k_attn_logits(const float* __restrict__ qkv, const float* __restrict__ edge,
                              const float* __restrict__ exp_w, const float* __restrict__ exp_b,
                              float* __restrict__ attn) {
    int z = blockIdx.z;
    int b = z >> 3, h = z & 7;
    int n0 = blockIdx.y * 64, m0 = blockIdx.x * 64;
    __shared__ __align__(16) float Qs[DH][68];
    __shared__ __align__(16) float Ks[DH][68];
    const float* qb = qkv + (size_t)b * NNODE * C3 + h * DH;
    const float* kb = qb + CC;
    int tid = threadIdx.y * 16 + threadIdx.x;
    for (int i = tid; i < 64 * DH; i += 256) {
        int r = i / DH, d = i - r * DH;
        Qs[d][r] = qb[(size_t)(n0 + r) * C3 + d];
        Ks[d][r] = kb[(size_t)(m0 + r) * C3 + d];
    }
    __syncthreads();
    float acc[4][4] = {};
#pragma unroll
    for (int kk = 0; kk < DH; kk++) {
        float4 a4 = *reinterpret_cast<const float4*>(&Qs[kk][threadIdx.y * 4]);
        float4 b4 = *reinterpret_cast<const float4*>(&Ks[kk][threadIdx.x * 4]);
        float av[4] = {a4.x, a4.y, a4.z, a4.w};
        float bv[4] = {b4.x, b4.y, b4.z, b4.w};
#pragma unroll
        for (int i = 0; i < 4; i++)
#pragma unroll
            for (int j = 0; j < 4; j++) acc[i][j] += av[i] * bv[j];
    }
    float ew = exp_w[h], eb = exp_b[h];
    const float* ebase = edge + ((size_t)b * NNODE + n0) * NNODE + m0;
    float* ap = attn + ((size_t)z * NNODE + n0) * NNODE + m0;
#pragma unroll
    for (int i = 0; i < 4; i++) {
        int r = threadIdx.y * 4 + i;
#pragma unroll
        for (int j = 0; j < 4; j++) {
            int c = threadIdx.x * 4 + j;
            ap[(size_t)r * NNODE + c] =
                acc[i][j] * ATTN_SCALE + ew * ebase[(size_t)r * NNODE + c] + eb;
        }
    }
}

// ---------------- per (b,n): softmax over heads, accumulate edge_new, attn := a --------
__global__ void k_attn_softmax_ednew(float* __restrict__ attn, float* __restrict__ ednew,
                                     const float* __restrict__ red_w,
                                     const float* __restrict__ red_b) {
    int bn = blockIdx.x;
    int b = bn >> 10, n = bn & 1023;
    __shared__ float row[NNODE];
    __shared__ float en[NNODE];
    __shared__ float red[256];
    int tid = threadIdx.x;
    for (int i = tid; i < NNODE; i += 256) en[i] = 0.f;
    __syncthreads();
    for (int h = 0; h < NH; h++) {
        float* ap = attn + (((size_t)(b * NH + h)) * NNODE + n) * NNODE;
        float lmax = -3.4e38f;
        for (int i = tid; i < NNODE; i += 256) {
            float v = ap[i];
            row[i] = v;
            lmax = fmaxf(lmax, v);
        }
        float mx = blockReduceMax(lmax, red);
        float ls = 0.f;
        for (int i = tid; i < NNODE; i += 256) ls += expf(row[i] - mx);
        float Z = blockReduceSum(ls, red);
        float invZ = 1.f / Z;
        float rw = red_w[h];
        for (int i = tid; i < NNODE; i += 256) {
            float a = expf(row[i] - mx) * invZ;
            en[i] += rw * (a + row[i]);
            ap[i] = a;
        }
        __syncthreads();
    }
    float rb = red_b[0];
    float* ep = ednew + (size_t)bn * NNODE;
    for (int i = tid; i < NNODE; i += 256) ep[i] = en[i] + rb;
}

// ---------------- AV: node_out[b,n,h*DH+d] = sum_m a[b,h,n,m]*v[b,m,h,d] ----------------
__global__ void k_av(const float* __restrict__ attn, const float* __restrict__ qkv,
                     float* __restrict__ node_out) {
    int z = blockIdx.y;
    int b = z >> 3, h = z & 7;
    int n0 = blockIdx.x * 64;
    __shared__ __align__(16) float As[16][68];
    __shared__ __align__(16) float Vs[16][68];
    const float* ap = attn + ((size_t)z * NNODE + n0) * NNODE;
    const float* vb = qkv + (size_t)b * NNODE * C3 + 2 * CC + h * DH;
    int tid = threadIdx.y * 16 + threadIdx.x;
    float acc[4][4] = {};
    for (int m0 = 0; m0 < NNODE; m0 += 16) {
        for (int i = tid; i < 64 * 16; i += 256) {
            int r = i >> 4, kk = i & 15;
            As[kk][r] = ap[(size_t)r * NNODE + m0 + kk];
        }
        for (int i = tid; i < 16 * 64; i += 256) {
            int kk = i >> 6, d = i & 63;
            Vs[kk][d] = (d < DH) ? vb[(size_t)(m0 + kk) * C3 + d] : 0.f;
        }
        __syncthreads();
#pragma unroll
        for (int kk = 0; kk < 16; kk++) {
            float4 a4 = *reinterpret_cast<const float4*>(&As[kk][threadIdx.y * 4]);
            float4 b4 = *reinterpret_cast<const float4*>(&Vs[kk][threadIdx.x * 4]);
            float av[4] = {a4.x, a4.y, a4.z, a4.w};
            float bv[4] = {b4.x, b4.y, b4.z, b4.w};
#pragma unroll
            for (int i = 0; i < 4; i++)
#pragma unroll
                for (int j = 0; j < 4; j++) acc[i][j] += av[i] * bv[j];
        }
        __syncthreads();
    }
#pragma unroll
    for (int i = 0; i < 4; i++) {
        int n = n0 + threadIdx.y * 4 + i;
#pragma unroll
        for (int j = 0; j < 4; j++) {
            int d = threadIdx.x * 4 + j;
            if (d < DH)
                node_out[((size_t)b * NNODE + n) * CC + h * DH + d] = acc[i][j];
        }
    }
}

// ------- per (b,n): ws=softmax(edge_new); wsum=sum(ws*edge_new); edge+=edge_new;
//         node_out += wsum --------
__global__ void k_ednew_post(float* __restrict__ edge, const float* __restrict__ ednew,
                             float* __restrict__ node_out) {
    int bn = blockIdx.x;
    __shared__ float row[NNODE];
    __shared__ float red[256];
    int tid = threadIdx.x;
    const float* ep = ednew + (size_t)bn * NNODE;
    float lmax = -3.4e38f;
    for (int i = tid; i < NNODE; i += 256) {
        float v = ep[i];
        row[i] = v;
        lmax = fmaxf(lmax, v);
    }
    float mx = blockReduceMax(lmax, red);
    float ls = 0.f, lS = 0.f;
    for (int i = tid; i < NNODE; i += 256) {
        float e = expf(row[i] - mx);
        ls += e;
        lS += e * row[i];
    }
    float Z = blockReduceSum(ls, red);
    float S = blockReduceSum(lS, red);
    float wsum = S / Z;
    float* eg = edge + (size_t)bn * NNODE;
    for (int i = tid; i < NNODE; i += 256) eg[i] += row[i];
    float* np = node_out + (size_t)bn * CC;
    for (int c = tid; c < CC; c += 256) np[c] += wsum;
}

// ---------------- launch ----------------
extern "C" void kernel_launch(void* const* d_in, const int* in_sizes, int n_in,
                              void* d_out, int out_size) {
    const float* x = (const float*)d_in[0];
    const float* da_prior = (const float*)d_in[1];
    const float* qk_w = (const float*)d_in[2];
    const float* fcp_w = (const float*)d_in[3];
    const float* fcp_b = (const float*)d_in[4];
    const float* ln1_g = (const float*)d_in[5];
    const float* ln1_b = (const float*)d_in[6];
    const float* gln_g = (const float*)d_in[7];
    const float* gln_b = (const float*)d_in[8];
    const float* qkv_w = (const float*)d_in[9];
    const float* qkv_b = (const float*)d_in[10];
    const float* proj_w = (const float*)d_in[11];
    const float* proj_b = (const float*)d_in[12];
    const float* exp_w = (const float*)d_in[13];
    const float* exp_b = (const float*)d_in[14];
    const float* red_w = (const float*)d_in[15];
    const float* red_b = (const float*)d_in[16];
    float* out = (float*)d_out;

    float *p_node, *p_qk, *p_y, *p_qkv, *p_edge, *p_ednew, *p_attn, *p_nodeout, *p_s;
    cudaGetSymbolAddress((void**)&p_node, g_node);
    cudaGetSymbolAddress((void**)&p_qk, g_qk);
    cudaGetSymbolAddress((void**)&p_y, g_y);
    cudaGetSymbolAddress((void**)&p_qkv, g_qkv);
    cudaGetSymbolAddress((void**)&p_edge, g_edge);
    cudaGetSymbolAddress((void**)&p_ednew, g_ednew);
    cudaGetSymbolAddress((void**)&p_attn, g_attn);
    cudaGetSymbolAddress((void**)&p_nodeout, g_nodeout);
    cudaGetSymbolAddress((void**)&p_s, g_s);

    dim3 t16(16, 16);

    // x -> node [B,N,C]
    k_tin<<<dim3(NNODE / 32, CC / 32, BB), dim3(32, 8)>>>(x, p_node);
    // prior sum
    k_prior<<<3, 256>>>(da_prior, fcp_w, fcp_b, p_s);
    // qk = node @ qk_w.T  : M=2048, N=640, K=320
    k_gemm_nt<<<dim3(C2 / 64, BB * NNODE / 64, 1), t16>>>(
        p_node, CC, 0, qk_w, CC, 0, p_qk, C2, 0, CC, 1.f, nullptr);
    // edge logits (batched over B): [1024,320]@[1024,320]^T
    k_gemm_nt<<<dim3(NNODE / 64, NNODE / 64, BB), t16>>>(
        p_qk, C2, (size_t)NNODE * C2, p_qk + CC, C2, (size_t)NNODE * C2,
        p_edge, NNODE, (size_t)NNODE * NNODE, CC, EDGE_SCALE, nullptr);
    k_row_softmax<<<BB * NNODE, 256>>>(p_edge);

    for (int l = 0; l < LLAYERS; l++) {
        k_ln_fuse<<<BB * NNODE, 256>>>(p_node, p_edge, p_s,
                                       ln1_g + l * CC, ln1_b + l * CC,
                                       gln_g + l * CC, gln_b + l * CC, p_y);
        // qkv = y @ qkv_w[l].T + qkv_b[l] : M=2048, N=960, K=320
        k_gemm_nt<<<dim3(C3 / 64, BB * NNODE / 64, 1), t16>>>(
            p_y, CC, 0, qkv_w + (size_t)l * C3 * CC, CC, 0,
            p_qkv, C3, 0, CC, 1.f, qkv_b + l * C3);
        k_attn_logits<<<dim3(NNODE / 64, NNODE / 64, BB * NH), t16>>>(
            p_qkv, p_edge, exp_w + l * NH, exp_b + l * NH, p_attn);
        k_attn_softmax_ednew<<<BB * NNODE, 256>>>(p_attn, p_ednew,
                                                  red_w + l * NH, red_b + l);
        k_av<<<dim3(NNODE / 64, BB * NH), t16>>>(p_attn, p_qkv, p_nodeout);
        k_ednew_post<<<BB * NNODE, 256>>>(p_edge, p_ednew, p_nodeout);
        // node = node_out @ proj_w[l].T + proj_b[l]
        k_gemm_nt<<<dim3(CC / 64, BB * NNODE / 64, 1), t16>>>(
            p_nodeout, CC, 0, proj_w + (size_t)l * CC * CC, CC, 0,
            p_node, CC, 0, CC, 1.f, proj_b + l * CC);
    }

    // node [B,N,C] -> out [B,C,N]
    k_tout<<<dim3(NNODE / 32, CC / 32, BB), dim3(32, 8)>>>(p_node, out);
}

// round 2
// speedup vs baseline: 1.7798x; 1.7798x over previous
#include <cuda_runtime.h>
#include <math.h>

// ---------------- problem constants ----------------
#define BB   2
#define CC   320
#define NNODE 1024
#define NH   8
#define DH   40
#define LLAYERS 2
#define C2   640
#define C3   960
#define AA   16
#define EPD  64

#define EDGE_SCALE 0.17677669529663687f  // 32^-0.5
#define ATTN_SCALE 0.15811388300841897f  // 40^-0.5
#define LN_EPS 1e-5f

// ---------------- scratch (static device globals; no runtime alloc) ----------------
static __device__ float g_node[BB * NNODE * CC];
static __device__ float g_qk[BB * NNODE * C2];
static __device__ float g_y[BB * NNODE * CC];
static __device__ float g_qkv[BB * NNODE * C3];
static __device__ float g_edge[BB * NNODE * NNODE];
static __device__ float g_ednew[BB * NNODE * NNODE];
static __device__ float g_attn[(size_t)BB * NH * NNODE * NNODE];
static __device__ float g_nodeout[BB * NNODE * CC];
static __device__ float g_s[BB * CC];

// ---------------- tf32 helpers ----------------
__device__ __forceinline__ unsigned f2tf(float f) {
    unsigned r;
    asm("cvt.rna.tf32.f32 %0, %1;" : "=r"(r) : "f"(f));
    return r;
}
__device__ __forceinline__ float f2tf_f(float f) {
    return __uint_as_float(f2tf(f));
}
__device__ __forceinline__ void mma_tf32(float (&c)[4], unsigned a0, unsigned a1,
                                         unsigned a2, unsigned a3, unsigned b0,
                                         unsigned b1) {
    asm volatile(
        "mma.sync.aligned.m16n8k8.row.col.f32.tf32.tf32.f32 "
        "{%0,%1,%2,%3},{%4,%5,%6,%7},{%8,%9},{%0,%1,%2,%3};"
        : "+f"(c[0]), "+f"(c[1]), "+f"(c[2]), "+f"(c[3])
        : "r"(a0), "r"(a1), "r"(a2), "r"(a3), "r"(b0), "r"(b1));
}

// ---------------- shuffle reductions (blockDim.x == 256) ----------------
__device__ __forceinline__ float warpRedSum(float v) {
#pragma unroll
    for (int o = 16; o; o >>= 1) v += __shfl_xor_sync(0xffffffffu, v, o);
    return v;
}
__device__ __forceinline__ float warpRedMax(float v) {
#pragma unroll
    for (int o = 16; o; o >>= 1) v = fmaxf(v, __shfl_xor_sync(0xffffffffu, v, o));
    return v;
}
__device__ __forceinline__ float blockSum(float v, float* sh) {
    v = warpRedSum(v);
    if ((threadIdx.x & 31) == 0) sh[threadIdx.x >> 5] = v;
    __syncthreads();
    float r = sh[0];
#pragma unroll
    for (int i = 1; i < 8; i++) r += sh[i];
    __syncthreads();
    return r;
}
__device__ __forceinline__ float blockMax(float v, float* sh) {
    v = warpRedMax(v);
    if ((threadIdx.x & 31) == 0) sh[threadIdx.x >> 5] = v;
    __syncthreads();
    float r = sh[0];
#pragma unroll
    for (int i = 1; i < 8; i++) r = fmaxf(r, sh[i]);
    __syncthreads();
    return r;
}

// ---------------- transposes ----------------
__global__ void k_tin(const float* __restrict__ x, float* __restrict__ node) {
    __shared__ float t[32][33];
    int b = blockIdx.z;
    int c0 = blockIdx.y * 32, n0 = blockIdx.x * 32;
#pragma unroll
    for (int i = 0; i < 4; i++)
        t[threadIdx.y + i * 8][threadIdx.x] =
            x[((size_t)b * CC + c0 + threadIdx.y + i * 8) * NNODE + n0 + threadIdx.x];
    __syncthreads();
#pragma unroll
    for (int i = 0; i < 4; i++)
        node[((size_t)b * NNODE + n0 + threadIdx.y + i * 8) * CC + c0 + threadIdx.x] =
            t[threadIdx.x][threadIdx.y + i * 8];
}

__global__ void k_tout(const float* __restrict__ node, float* __restrict__ out) {
    __shared__ float t[32][33];
    int b = blockIdx.z;
    int c0 = blockIdx.y * 32, n0 = blockIdx.x * 32;
#pragma unroll
    for (int i = 0; i < 4; i++)
        t[threadIdx.y + i * 8][threadIdx.x] =
            node[((size_t)b * NNODE + n0 + threadIdx.y + i * 8) * CC + c0 + threadIdx.x];
    __syncthreads();
#pragma unroll
    for (int i = 0; i < 4; i++)
        out[((size_t)b * CC + c0 + threadIdx.y + i * 8) * NNODE + n0 + threadIdx.x] =
            t[threadIdx.x][threadIdx.y + i * 8];
}

// ---------------- prior sum ----------------
__global__ void k_prior(const float* __restrict__ da, const float* __restrict__ w,
                        const float* __restrict__ bfc, float* __restrict__ s) {
    int t = blockIdx.x * blockDim.x + threadIdx.x;
    if (t >= BB * CC) return;
    int b = t / CC, c = t % CC;
    float acc = (float)AA * bfc[c];
    for (int e = 0; e < EPD; e++) {
        float sa = 0.f;
#pragma unroll
        for (int a = 0; a < AA; a++) sa += da[((size_t)b * AA + a) * EPD + e];
        acc += sa * w[c * EPD + e];
    }
    s[t] = acc;
}

// ============ generic tf32 NT GEMM: C = alpha*A@W^T (+bias) ============
// tile 128x64, 256 thr = 8 warps (4m x 2n), warp 32x32, TK=16.
// pitches 136/72 (==8 mod 32) for conflict-free fragment LDS.
__global__ void k_mm(const float* __restrict__ A, int lda, size_t sA,
                     const float* __restrict__ W, int ldw, size_t sW,
                     float* __restrict__ Cc, int ldc, size_t sC, int K, float alpha,
                     const float* __restrict__ bias) {
    int bz = blockIdx.z;
    A += (size_t)bz * sA;
    W += (size_t)bz * sW;
    Cc += (size_t)bz * sC;
    __shared__ float As[16][136];
    __shared__ float Ws[16][72];
    int m0 = blockIdx.y * 128, n0 = blockIdx.x * 64;
    int tid = threadIdx.x;
    int warp = tid >> 5, lane = tid & 31;
    int wm = (warp >> 1) * 32, wn = (warp & 1) * 32;
    int lq = lane >> 2, lr = lane & 3;
    float acc[2][4][4] = {};
    for (int k0 = 0; k0 < K; k0 += 16) {
#pragma unroll
        for (int i = 0; i < 8; i++) {
            int idx = tid + i * 256;
            int kk = idx & 15, r = idx >> 4;
            As[kk][r] = f2tf_f(A[(size_t)(m0 + r) * lda + k0 + kk]);
        }
#pragma unroll
        for (int i = 0; i < 4; i++) {
            int idx = tid + i * 256;
            int kk = idx & 15, r = idx >> 4;
            Ws[kk][r] = f2tf_f(W[(size_t)(n0 + r) * ldw + k0 + kk]);
        }
        __syncthreads();
#pragma unroll
        for (int kh = 0; kh < 2; kh++) {
            int kb = kh * 8;
            unsigned a[2][4], b[4][2];
#pragma unroll
            for (int mt = 0; mt < 2; mt++) {
                int mb = wm + mt * 16;
                a[mt][0] = __float_as_uint(As[kb + lr][mb + lq]);
                a[mt][1] = __float_as_uint(As[kb + lr][mb + lq + 8]);
                a[mt][2] = __float_as_uint(As[kb + 4 + lr][mb + lq]);
                a[mt][3] = __float_as_uint(As[kb + 4 + lr][mb + lq + 8]);
            }
#pragma unroll
            for (int nt = 0; nt < 4; nt++) {
                int nb = wn + nt * 8;
                b[nt][0] = __float_as_uint(Ws[kb + lr][nb + lq]);
                b[nt][1] = __float_as_uint(Ws[kb + 4 + lr][nb + lq]);
            }
#pragma unroll
            for (int mt = 0; mt < 2; mt++)
#pragma unroll
                for (int nt = 0; nt < 4; nt++)
                    mma_tf32(acc[mt][nt], a[mt][0], a[mt][1], a[mt][2], a[mt][3],
                             b[nt][0], b[nt][1]);
        }
        __syncthreads();
    }
#pragma unroll
    for (int mt = 0; mt < 2; mt++) {
#pragma unroll
        for (int nt = 0; nt < 4; nt++) {
            int gc = n0 + wn + nt * 8 + 2 * lr;
            float bi0 = bias ? bias[gc] : 0.f;
            float bi1 = bias ? bias[gc + 1] : 0.f;
#pragma unroll
            for (int half = 0; half < 2; half++) {
                int gr = m0 + wm + mt * 16 + lq + half * 8;
                float2 v;
                v.x = alpha * acc[mt][nt][half * 2] + bi0;
                v.y = alpha * acc[mt][nt][half * 2 + 1] + bi1;
                *reinterpret_cast<float2*>(&Cc[(size_t)gr * ldc + gc]) = v;
            }
        }
    }
}

// ============ attn logits tf32: attn = SCALE*q@k^T + ew*edge + eb ============
// tile 128(n) x 64(m), K = DH = 40, TK=8.
__global__ void k_logits(const float* __restrict__ qkv, const float* __restrict__ edge,
                         const float* __restrict__ exp_w, const float* __restrict__ exp_b,
                         float* __restrict__ attn) {
    int z = blockIdx.z;
    int b = z >> 3, h = z & 7;
    const float* Aq = qkv + (size_t)b * NNODE * C3 + h * DH;
    const float* Wk = Aq + CC;
    __shared__ float As[8][136];
    __shared__ float Ws[8][72];
    int m0 = blockIdx.y * 128, n0 = blockIdx.x * 64;
    int tid = threadIdx.x;
    int warp = tid >> 5, lane = tid & 31;
    int wm = (warp >> 1) * 32, wn = (warp & 1) * 32;
    int lq = lane >> 2, lr = lane & 3;
    float acc[2][4][4] = {};
    for (int k0 = 0; k0 < DH; k0 += 8) {
#pragma unroll
        for (int i = 0; i < 4; i++) {
            int idx = tid + i * 256;
            int kk = idx & 7, r = idx >> 3;
            As[kk][r] = f2tf_f(Aq[(size_t)(m0 + r) * C3 + k0 + kk]);
        }
#pragma unroll
        for (int i = 0; i < 2; i++) {
            int idx = tid + i * 256;
            int kk = idx & 7, r = idx >> 3;
            Ws[kk][r] = f2tf_f(Wk[(size_t)(n0 + r) * C3 + k0 + kk]);
        }
        __syncthreads();
        unsigned a[2][4], bf[4][2];
#pragma unroll
        for (int mt = 0; mt < 2; mt++) {
            int mb = wm + mt * 16;
            a[mt][0] = __float_as_uint(As[lr][mb + lq]);
            a[mt][1] = __float_as_uint(As[lr][mb + lq + 8]);
            a[mt][2] = __float_as_uint(As[4 + lr][mb + lq]);
            a[mt][3] = __float_as_uint(As[4 + lr][mb + lq + 8]);
        }
#pragma unroll
        for (int nt = 0; nt < 4; nt++) {
            int nb = wn + nt * 8;
            bf[nt][0] = __float_as_uint(Ws[lr][nb + lq]);
            bf[nt][1] = __float_as_uint(Ws[4 + lr][nb + lq]);
        }
#pragma unroll
        for (int mt = 0; mt < 2; mt++)
#pragma unroll
            for (int nt = 0; nt < 4; nt++)
                mma_tf32(acc[mt][nt], a[mt][0], a[mt][1], a[mt][2], a[mt][3],
                         bf[nt][0], bf[nt][1]);
        __syncthreads();
    }
    float ew = exp_w[h], eb = exp_b[h];
    const float* ebase = edge + (size_t)b * NNODE * NNODE;
    float* ap = attn + (size_t)z * NNODE * NNODE;
#pragma unroll
    for (int mt = 0; mt < 2; mt++) {
#pragma unroll
        for (int nt = 0; nt < 4; nt++) {
            int gc = n0 + wn + nt * 8 + 2 * lr;
#pragma unroll
            for (int half = 0; half < 2; half++) {
                int gr = m0 + wm + mt * 16 + lq + half * 8;
                float2 e2 = *reinterpret_cast<const float2*>(
                    &ebase[(size_t)gr * NNODE + gc]);
                float2 v;
                v.x = acc[mt][nt][half * 2] * ATTN_SCALE + ew * e2.x + eb;
                v.y = acc[mt][nt][half * 2 + 1] * ATTN_SCALE + ew * e2.y + eb;
                *reinterpret_cast<float2*>(&ap[(size_t)gr * NNODE + gc]) = v;
            }
        }
    }
}

// ============ AV tf32: node_out[b,n,h*DH+d] = sum_m a[bh,n,m] v[b,m,h,d] ============
// tile 64(n) x 40(d), 4 warps (16 rows each), K=1024 in TK=8 steps.
__global__ void k_av(const float* __restrict__ attn, const float* __restrict__ qkv,
                     float* __restrict__ node_out) {
    int z = blockIdx.y;
    int b = z >> 3, h = z & 7;
    int n0 = blockIdx.x * 64;
    const float* ap = attn + ((size_t)z * NNODE + n0) * NNODE;
    const float* vb = qkv + (size_t)b * NNODE * C3 + 2 * CC + h * DH;
    __shared__ float As[8][72];
    __shared__ float Vs[8][40];
    int tid = threadIdx.x;  // 128
    int warp = tid >> 5, lane = tid & 31;
    int lq = lane >> 2, lr = lane & 3;
    float acc[5][4] = {};
    for (int m0 = 0; m0 < NNODE; m0 += 8) {
#pragma unroll
        for (int i = 0; i < 4; i++) {
            int idx = tid + i * 128;
            int kk = idx & 7, r = idx >> 3;
            As[kk][r] = f2tf_f(ap[(size_t)r * NNODE + m0 + kk]);
        }
#pragma unroll
        for (int i = 0; i < 3; i++) {
            int idx = tid + i * 128;
            if (idx < 320) {
                int kk = idx / 40, d = idx - kk * 40;
                Vs[kk][d] = f2tf_f(vb[(size_t)(m0 + kk) * C3 + d]);
            }
        }
        __syncthreads();
        int mb = warp * 16;
        unsigned a0 = __float_as_uint(As[lr][mb + lq]);
        unsigned a1 = __float_as_uint(As[lr][mb + lq + 8]);
        unsigned a2 = __float_as_uint(As[4 + lr][mb + lq]);
        unsigned a3 = __float_as_uint(As[4 + lr][mb + lq + 8]);
#pragma unroll
        for (int nt = 0; nt < 5; nt++) {
            unsigned b0 = __float_as_uint(Vs[lr][nt * 8 + lq]);
            unsigned b1 = __float_as_uint(Vs[4 + lr][nt * 8 + lq]);
            mma_tf32(acc[nt], a0, a1, a2, a3, b0, b1);
        }
        __syncthreads();
    }
#pragma unroll
    for (int nt = 0; nt < 5; nt++) {
        int gd = nt * 8 + 2 * lr;
#pragma unroll
        for (int half = 0; half < 2; half++) {
            int gn = n0 + warp * 16 + lq + half * 8;
            float2 v;
            v.x = acc[nt][half * 2];
            v.y = acc[nt][half * 2 + 1];
            *reinterpret_cast<float2*>(
                &node_out[((size_t)b * NNODE + gn) * CC + h * DH + gd]) = v;
        }
    }
}

// ---------------- row softmax in-place on [B*N, N] ----------------
__global__ void k_row_softmax(float* __restrict__ E) {
    size_t off = (size_t)blockIdx.x * NNODE;
    __shared__ float row[NNODE];
    __shared__ float sh[8];
    int tid = threadIdx.x;
    float lmax = -3.4e38f;
    for (int i = tid; i < NNODE; i += 256) {
        float v = E[off + i];
        row[i] = v;
        lmax = fmaxf(lmax, v);
    }
    float mx = blockMax(lmax, sh);
    float ls = 0.f;
    for (int i = tid; i < NNODE; i += 256) {
        float e = __expf(row[i] - mx);
        row[i] = e;
        ls += e;
    }
    float Z = blockSum(ls, sh);
    float invZ = 1.f / Z;
    for (int i = tid; i < NNODE; i += 256) E[off + i] = row[i] * invZ;
}

// ---------------- fused LN1 + graph-mix + LN2 ----------------
__global__ void k_ln_fuse(const float* __restrict__ node, const float* __restrict__ edge,
                          const float* __restrict__ s,
                          const float* __restrict__ g1, const float* __restrict__ b1,
                          const float* __restrict__ g2, const float* __restrict__ b2,
                          float* __restrict__ y) {
    int bn = blockIdx.x;
    int b = bn >> 10, n = bn & 1023;
    __shared__ float row[CC];
    __shared__ float sh[8];
    int tid = threadIdx.x;
    const float* xr = node + (size_t)bn * CC;
    float lsum = 0.f, lsq = 0.f;
    for (int c = tid; c < CC; c += 256) {
        float v = xr[c];
        row[c] = v;
        lsum += v;
        lsq += v * v;
    }
    float sum = blockSum(lsum, sh);
    float sq = blockSum(lsq, sh);
    float mean = sum * (1.f / CC);
    float var = sq * (1.f / CC) - mean * mean;
    float inv = rsqrtf(var + LN_EPS);
    float diag = edge[((size_t)b * NNODE + n) * NNODE + n];
    lsum = 0.f;
    lsq = 0.f;
    for (int c = tid; c < CC; c += 256) {
        float nt = (row[c] - mean) * inv * g1[c] + b1[c];
        float n2 = diag * nt * s[b * CC + c] + nt;
        row[c] = n2;
        lsum += n2;
        lsq += n2 * n2;
    }
    float sum2 = blockSum(lsum, sh);
    float sq2 = blockSum(lsq, sh);
    float mean2 = sum2 * (1.f / CC);
    float var2 = sq2 * (1.f / CC) - mean2 * mean2;
    float inv2 = rsqrtf(var2 + LN_EPS);
    float* yr = y + (size_t)bn * CC;
    for (int c = tid; c < CC; c += 256)
        yr[c] = (row[c] - mean2) * inv2 * g2[c] + b2[c];
}

// ---------------- per (b,n): softmax heads, accumulate edge_new, attn := a ----------
__global__ void k_attn_softmax_ednew(float* __restrict__ attn, float* __restrict__ ednew,
                                     const float* __restrict__ red_w,
                                     const float* __restrict__ red_b) {
    int bn = blockIdx.x;
    int b = bn >> 10, n = bn & 1023;
    __shared__ float row[NNODE];
    __shared__ float ex[NNODE];
    __shared__ float en[NNODE];
    __shared__ float sh[8];
    int tid = threadIdx.x;
    for (int i = tid; i < NNODE; i += 256) en[i] = 0.f;
    __syncthreads();
    for (int h = 0; h < NH; h++) {
        float* ap = attn + (((size_t)(b * NH + h)) * NNODE + n) * NNODE;
        float lmax = -3.4e38f;
        for (int i = tid; i < NNODE; i += 256) {
            float v = ap[i];
            row[i] = v;
            lmax = fmaxf(lmax, v);
        }
        float mx = blockMax(lmax, sh);
        float ls = 0.f;
        for (int i = tid; i < NNODE; i += 256) {
            float e = __expf(row[i] - mx);
            ex[i] = e;
            ls += e;
        }
        float Z = blockSum(ls, sh);
        float invZ = 1.f / Z;
        float rw = red_w[h];
        for (int i = tid; i < NNODE; i += 256) {
            float a = ex[i] * invZ;
            en[i] += rw * (a + row[i]);
            ap[i] = a;
        }
        __syncthreads();
    }
    float rb = red_b[0];
    float* ep = ednew + (size_t)bn * NNODE;
    for (int i = tid; i < NNODE; i += 256) ep[i] = en[i] + rb;
}

// ------- per (b,n): wsum from softmax(edge_new); edge+=ednew; node_out+=wsum -------
__global__ void k_ednew_post(float* __restrict__ edge, const float* __restrict__ ednew,
                             float* __restrict__ node_out) {
    int bn = blockIdx.x;
    __shared__ float row[NNODE];
    __shared__ float sh[8];
    int tid = threadIdx.x;
    const float* ep = ednew + (size_t)bn * NNODE;
    float lmax = -3.4e38f;
    for (int i = tid; i < NNODE; i += 256) {
        float v = ep[i];
        row[i] = v;
        lmax = fmaxf(lmax, v);
    }
    float mx = blockMax(lmax, sh);
    float ls = 0.f, lS = 0.f;
    for (int i = tid; i < NNODE; i += 256) {
        float e = __expf(row[i] - mx);
        ls += e;
        lS += e * row[i];
    }
    float Z = blockSum(ls, sh);
    float S = blockSum(lS, sh);
    float wsum = S / Z;
    float* eg = edge + (size_t)bn * NNODE;
    for (int i = tid; i < NNODE; i += 256) eg[i] += row[i];
    float* np = node_out + (size_t)bn * CC;
    for (int c = tid; c < CC; c += 256) np[c] += wsum;
}

// ---------------- launch ----------------
extern "C" void kernel_launch(void* const* d_in, const int* in_sizes, int n_in,
                              void* d_out, int out_size) {
    const float* x = (const float*)d_in[0];
    const float* da_prior = (const float*)d_in[1];
    const float* qk_w = (const float*)d_in[2];
    const float* fcp_w = (const float*)d_in[3];
    const float* fcp_b = (const float*)d_in[4];
    const float* ln1_g = (const float*)d_in[5];
    const float* ln1_b = (const float*)d_in[6];
    const float* gln_g = (const float*)d_in[7];
    const float* gln_b = (const float*)d_in[8];
    const float* qkv_w = (const float*)d_in[9];
    const float* qkv_b = (const float*)d_in[10];
    const float* proj_w = (const float*)d_in[11];
    const float* proj_b = (const float*)d_in[12];
    const float* exp_w = (const float*)d_in[13];
    const float* exp_b = (const float*)d_in[14];
    const float* red_w = (const float*)d_in[15];
    const float* red_b = (const float*)d_in[16];
    float* out = (float*)d_out;

    float *p_node, *p_qk, *p_y, *p_qkv, *p_edge, *p_ednew, *p_attn, *p_nodeout, *p_s;
    cudaGetSymbolAddress((void**)&p_node, g_node);
    cudaGetSymbolAddress((void**)&p_qk, g_qk);
    cudaGetSymbolAddress((void**)&p_y, g_y);
    cudaGetSymbolAddress((void**)&p_qkv, g_qkv);
    cudaGetSymbolAddress((void**)&p_edge, g_edge);
    cudaGetSymbolAddress((void**)&p_ednew, g_ednew);
    cudaGetSymbolAddress((void**)&p_attn, g_attn);
    cudaGetSymbolAddress((void**)&p_nodeout, g_nodeout);
    cudaGetSymbolAddress((void**)&p_s, g_s);

    // x -> node [B,N,C]
    k_tin<<<dim3(NNODE / 32, CC / 32, BB), dim3(32, 8)>>>(x, p_node);
    k_prior<<<3, 256>>>(da_prior, fcp_w, fcp_b, p_s);
    // qk = node @ qk_w.T : M=2048, N=640, K=320
    k_mm<<<dim3(C2 / 64, (BB * NNODE) / 128, 1), 256>>>(
        p_node, CC, 0, qk_w, CC, 0, p_qk, C2, 0, CC, 1.f, nullptr);
    // edge logits per batch: [1024,320]@[1024,320]^T
    k_mm<<<dim3(NNODE / 64, NNODE / 128, BB), 256>>>(
        p_qk, C2, (size_t)NNODE * C2, p_qk + CC, C2, (size_t)NNODE * C2,
        p_edge, NNODE, (size_t)NNODE * NNODE, CC, EDGE_SCALE, nullptr);
    k_row_softmax<<<BB * NNODE, 256>>>(p_edge);

    for (int l = 0; l < LLAYERS; l++) {
        k_ln_fuse<<<BB * NNODE, 256>>>(p_node, p_edge, p_s,
                                       ln1_g + l * CC, ln1_b + l * CC,
                                       gln_g + l * CC, gln_b + l * CC, p_y);
        // qkv : M=2048, N=960, K=320
        k_mm<<<dim3(C3 / 64, (BB * NNODE) / 128, 1), 256>>>(
            p_y, CC, 0, qkv_w + (size_t)l * C3 * CC, CC, 0,
            p_qkv, C3, 0, CC, 1.f, qkv_b + l * C3);
        k_logits<<<dim3(NNODE / 64, NNODE / 128, BB * NH), 256>>>(
            p_qkv, p_edge, exp_w + l * NH, exp_b + l * NH, p_attn);
        k_attn_softmax_ednew<<<BB * NNODE, 256>>>(p_attn, p_ednew,
                                                  red_w + l * NH, red_b + l);
        k_av<<<dim3(NNODE / 64, BB * NH), 128>>>(p_attn, p_qkv, p_nodeout);
        k_ednew_post<<<BB * NNODE, 256>>>(p_edge, p_ednew, p_nodeout);
        // proj : M=2048, N=320, K=320
        k_mm<<<dim3(CC / 64, (BB * NNODE) / 128, 1), 256>>>(
            p_nodeout, CC, 0, proj_w + (size_t)l * CC * CC, CC, 0,
            p_node, CC, 0, CC, 1.f, proj_b + l * CC);
    }

    k_tout<<<dim3(NNODE / 32, CC / 32, BB), dim3(32, 8)>>>(p_node, out);
}